// round 8
// baseline (speedup 1.0000x reference)
#include <cuda_runtime.h>
#include <cstdint>

// real, pred: [128, 8192, 8] fp32. Row = 8 classes.
// loss = 1 - mean_over_rows( all_c( (pred>0.5) == real ) )

static constexpr int TPB = 256;
static constexpr long long NROWS = 1048576;          // 2^20
static constexpr int BLOCKS = 1024;                  // 1024 rows per block
static constexpr int ROWS_PER_BLOCK = (int)(NROWS / BLOCKS);   // 1024
static constexpr int TILE_ROWS = 256;                // rows per stage
static constexpr int TILE_BYTES = TILE_ROWS * 32;    // 8192 B per tensor
static constexpr int STAGES = 2;
static constexpr int ITERS = ROWS_PER_BLOCK / TILE_ROWS;       // 4

__device__ unsigned int g_count = 0;
__device__ unsigned int g_done  = 0;

__device__ __forceinline__ uint32_t smem_u32(const void* p) {
    uint32_t a;
    asm("{ .reg .u64 t; cvta.to.shared.u64 t, %1; cvt.u32.u64 %0, t; }" : "=r"(a) : "l"(p));
    return a;
}

__device__ __forceinline__ void mbar_init(uint32_t mbar, uint32_t count) {
    asm volatile("mbarrier.init.shared.b64 [%0], %1;" :: "r"(mbar), "r"(count) : "memory");
}
__device__ __forceinline__ void mbar_expect_tx(uint32_t mbar, uint32_t bytes) {
    asm volatile("mbarrier.arrive.expect_tx.shared.b64 _, [%0], %1;" :: "r"(mbar), "r"(bytes) : "memory");
}
__device__ __forceinline__ void mbar_arrive(uint32_t mbar) {
    asm volatile("mbarrier.arrive.shared.b64 _, [%0];" :: "r"(mbar) : "memory");
}
__device__ __forceinline__ void mbar_wait(uint32_t mbar, uint32_t parity) {
    asm volatile(
        "{\n\t.reg .pred P;\n"
        "WAIT_%=:\n\t"
        "mbarrier.try_wait.parity.acquire.cta.shared::cta.b64 P, [%0], %1, 0x989680;\n\t"
        "@P bra.uni DONE_%=;\n\t"
        "bra.uni WAIT_%=;\n"
        "DONE_%=:\n\t}"
        :: "r"(mbar), "r"(parity) : "memory");
}
__device__ __forceinline__ void bulk_g2s(uint32_t dst, const void* src, uint32_t bytes, uint32_t mbar) {
    asm volatile(
        "cp.async.bulk.shared::cluster.global.mbarrier::complete_tx::bytes [%0], [%1], %2, [%3];"
        :: "r"(dst), "l"(src), "r"(bytes), "r"(mbar) : "memory");
}

__global__ __launch_bounds__(TPB) void fused_kernel(
    const float* __restrict__ real_, const float* __restrict__ pred_,
    float* __restrict__ out)
{
    __shared__ __align__(128) float4 s_real[STAGES][TILE_BYTES / 16];
    __shared__ __align__(128) float4 s_pred[STAGES][TILE_BYTES / 16];
    __shared__ __align__(8) unsigned long long mb_full[STAGES];
    __shared__ __align__(8) unsigned long long mb_empty[STAGES];
    __shared__ int red[TPB / 32];

    const int tid = threadIdx.x;
    uint32_t full_a[STAGES], empty_a[STAGES];
#pragma unroll
    for (int s = 0; s < STAGES; s++) {
        full_a[s]  = smem_u32(&mb_full[s]);
        empty_a[s] = smem_u32(&mb_empty[s]);
    }

    if (tid == 0) {
#pragma unroll
        for (int s = 0; s < STAGES; s++) {
            mbar_init(full_a[s], 1);      // producer's expect_tx is the single arrival
            mbar_init(empty_a[s], TPB);   // every thread arrives after consuming
        }
        asm volatile("fence.proxy.async.shared::cta;" ::: "memory");
    }
    __syncthreads();

    const long long row0 = (long long)blockIdx.x * ROWS_PER_BLOCK;
    int local = 0;

#pragma unroll
    for (int it = 0; it < ITERS; it++) {
        const int s = it & (STAGES - 1);
        const int k = it / STAGES;            // use-count of this stage

        if (tid == 0) {
            if (it >= STAGES) mbar_wait(empty_a[s], (k - 1) & 1);
            mbar_expect_tx(full_a[s], 2 * TILE_BYTES);
            const float* rsrc = real_ + (row0 + (long long)it * TILE_ROWS) * 8;
            const float* psrc = pred_ + (row0 + (long long)it * TILE_ROWS) * 8;
            bulk_g2s(smem_u32(&s_real[s][0]), rsrc, TILE_BYTES, full_a[s]);
            bulk_g2s(smem_u32(&s_pred[s][0]), psrc, TILE_BYTES, full_a[s]);
        }

        mbar_wait(full_a[s], k & 1);

        // Consume: 2 passes; lane reads contiguous 16B (conflict-free LDS.128).
        // Each lane checks half a row (4 classes); pair (t, t^1) combines.
#pragma unroll
        for (int pass = 0; pass < 2; pass++) {
            const int c = pass * TPB + tid;          // 16B-chunk index, 0..511
            float4 rv = s_real[s][c];
            float4 pv = s_pred[s][c];
            int m =
                ((pv.x > 0.5f) == (rv.x != 0.0f)) &
                ((pv.y > 0.5f) == (rv.y != 0.0f)) &
                ((pv.z > 0.5f) == (rv.z != 0.0f)) &
                ((pv.w > 0.5f) == (rv.w != 0.0f));
            int both = m & __shfl_xor_sync(0xFFFFFFFFu, m, 1);
            local += ((tid & 1) == 0) ? both : 0;
        }

        mbar_arrive(empty_a[s]);
    }

    // block reduction
    local = __reduce_add_sync(0xFFFFFFFFu, local);
    if ((tid & 31) == 0) red[tid >> 5] = local;
    __syncthreads();

    if (tid == 0) {
        int t = 0;
#pragma unroll
        for (int w = 0; w < TPB / 32; w++) t += red[w];
        atomicAdd(&g_count, (unsigned int)t);

        __threadfence();
        unsigned int ticket = atomicAdd(&g_done, 1u);
        if (ticket == (unsigned int)(BLOCKS - 1)) {
            unsigned int total = g_count;
            *out = 1.0f - (float)total * (1.0f / (float)NROWS);
            g_count = 0u;
            g_done = 0u;
        }
    }
}

extern "C" void kernel_launch(void* const* d_in, const int* in_sizes, int n_in,
                              void* d_out, int out_size) {
    const float* real_ = (const float*)d_in[0];
    const float* pred_ = (const float*)d_in[1];
    float* out = (float*)d_out;

    fused_kernel<<<BLOCKS, TPB>>>(real_, pred_, out);
}

// round 9
// speedup vs baseline: 1.1910x; 1.1910x over previous
#include <cuda_runtime.h>
#include <cstdint>

// real, pred: [128, 8192, 8] fp32. Row = 8 classes.
// loss = 1 - mean_over_rows( all_c( (pred>0.5) == real ) )

static constexpr int B = 128;
static constexpr int L = 8192;
static constexpr long long NROWS = (long long)B * L;      // 1,048,576
static constexpr int TPB = 128;
static constexpr int RPT = 2;                              // rows per thread
static constexpr int BLOCKS = (int)(NROWS / (TPB * RPT));  // 4096

__device__ unsigned int g_count = 0;   // correct-row count
__device__ unsigned int g_done  = 0;   // finished-block ticket counter

// Blackwell 256-bit global load: one LDG.E.256 fetches a full 8-float row.
__device__ __forceinline__ void ldg256(const float* p, float4& a, float4& b) {
    asm volatile("ld.global.v8.f32 {%0,%1,%2,%3,%4,%5,%6,%7}, [%8];"
        : "=f"(a.x), "=f"(a.y), "=f"(a.z), "=f"(a.w),
          "=f"(b.x), "=f"(b.y), "=f"(b.z), "=f"(b.w)
        : "l"(p));
}

__device__ __forceinline__ int row_ok(float4 r0, float4 r1, float4 p0, float4 p1) {
    // real is exactly 0.0f or 1.0f; predicted label = (pred > 0.5f)
    bool ok =
        ((p0.x > 0.5f) == (r0.x != 0.0f)) &
        ((p0.y > 0.5f) == (r0.y != 0.0f)) &
        ((p0.z > 0.5f) == (r0.z != 0.0f)) &
        ((p0.w > 0.5f) == (r0.w != 0.0f)) &
        ((p1.x > 0.5f) == (r1.x != 0.0f)) &
        ((p1.y > 0.5f) == (r1.y != 0.0f)) &
        ((p1.z > 0.5f) == (r1.z != 0.0f)) &
        ((p1.w > 0.5f) == (r1.w != 0.0f));
    return (int)ok;
}

__global__ __launch_bounds__(TPB) void fused_kernel(
    const float* __restrict__ real_, const float* __restrict__ pred_,
    float* __restrict__ out)
{
    const int stride = TPB * BLOCKS;               // rows per sweep
    int base = blockIdx.x * TPB + threadIdx.x;

    // Front-batch all 4 LDG.256 (2 rows x {real,pred}); 32 data regs.
    float4 r[RPT][2], p[RPT][2];
#pragma unroll
    for (int i = 0; i < RPT; i++) {
        int row = base + i * stride;
        ldg256(real_ + 8ll * row, r[i][0], r[i][1]);
        ldg256(pred_ + 8ll * row, p[i][0], p[i][1]);
    }

    int local = 0;
#pragma unroll
    for (int i = 0; i < RPT; i++)
        local += row_ok(r[i][0], r[i][1], p[i][0], p[i][1]);

    // warp reduce
    local = __reduce_add_sync(0xFFFFFFFFu, local);

    __shared__ int smem[TPB / 32];
    if ((threadIdx.x & 31) == 0) smem[threadIdx.x >> 5] = local;
    __syncthreads();

    if (threadIdx.x == 0) {
        int t = 0;
#pragma unroll
        for (int w = 0; w < TPB / 32; w++) t += smem[w];
        atomicAdd(&g_count, (unsigned int)t);

        // last block finalizes and resets state for the next graph replay
        __threadfence();
        unsigned int ticket = atomicAdd(&g_done, 1u);
        if (ticket == (unsigned int)(BLOCKS - 1)) {
            unsigned int total = g_count;
            *out = 1.0f - (float)total * (1.0f / (float)NROWS);
            g_count = 0u;
            g_done = 0u;
        }
    }
}

extern "C" void kernel_launch(void* const* d_in, const int* in_sizes, int n_in,
                              void* d_out, int out_size) {
    const float* real_ = (const float*)d_in[0];
    const float* pred_ = (const float*)d_in[1];
    float* out = (float*)d_out;

    fused_kernel<<<BLOCKS, TPB>>>(real_, pred_, out);
}